// round 15
// baseline (speedup 1.0000x reference)
#include <cuda_runtime.h>
#include <cuda_fp16.h>
#include <cstdint>

// ===========================================================================
// GraphConvLayer, v9: src-sorted edges + tile-local segmented reduction.
//   sort (hist/scan/scatter) groups edges by src; the edge kernel computes
//   H = lrelu(P[dst] + ef@W1b) into an fp32 smem buffer and flushes one
//   red.v4 per (src-run, col-group) instead of one per row -> ~5x fewer
//   global atomics. deg comes free from the histogram.
// ===========================================================================

#define MAX_N 50000
#define MAX_E 800000

__device__ float  g_agg[(size_t)MAX_N * 128];
__device__ int    g_cnt[MAX_N];
__device__ int    g_pos[MAX_N];
__device__ float  g_vc[128];
__device__ __half g_Ph[(size_t)MAX_N * 128];
__device__ int    g_src[MAX_E];
__device__ int    g_dst[MAX_E];
__device__ int    g_ssrc[MAX_E];
__device__ int    g_sdst[MAX_E];
__device__ int    g_seid[MAX_E];
__device__ __half g_nfh[(size_t)MAX_N * 128];
__device__ __half g_nfl[(size_t)MAX_N * 128];
// weight images: W1Ma hi(perm,136) W1Mb hi(perm,72) W1U hi(264, k>=128 = Wc) W2U hi/lo(perm,136)
__device__ __half g_wimg[112640];

#define HW_W1MA 0
#define HW_W1MB 17408
#define HW_W1U  26624
#define HW_W2UH 60416
#define HW_W2UL 77824
#define BW_W1MA 0
#define BW_W1MB 34816
#define BW_W1U  53248
#define BW_W2U  120832   // hi+lo contiguous 69632

// ---------------- helpers ----------------
__device__ __forceinline__ uint32_t smem_u32(const void* p) {
    uint32_t a;
    asm("{ .reg .u64 t; cvta.to.shared.u64 t, %1; cvt.u32.u64 %0, t; }" : "=r"(a) : "l"(p));
    return a;
}
__device__ __forceinline__ float lrelu(float v) { return v >= 0.f ? v : 0.2f * v; }
__device__ __forceinline__ uint32_t packh2(__half a, __half b) {
    __half2 h = __halves2half2(a, b);
    return *reinterpret_cast<uint32_t*>(&h);
}
__device__ __forceinline__ float2 unp2(uint32_t u) {
    __half2 h = *reinterpret_cast<__half2*>(&u);
    return __half22float2(h);
}
__device__ __forceinline__ void ldsm4(uint32_t* r, uint32_t a) {
    asm volatile("ldmatrix.sync.aligned.m8n8.x4.shared.b16 {%0,%1,%2,%3}, [%4];"
        : "=r"(r[0]), "=r"(r[1]), "=r"(r[2]), "=r"(r[3]) : "r"(a));
}
__device__ __forceinline__ void mma16816(float* c, const uint32_t* a, uint32_t b0, uint32_t b1) {
    asm volatile("mma.sync.aligned.m16n8k16.row.col.f32.f16.f16.f32 "
        "{%0,%1,%2,%3}, {%4,%5,%6,%7}, {%8,%9}, {%0,%1,%2,%3};"
        : "+f"(c[0]), "+f"(c[1]), "+f"(c[2]), "+f"(c[3])
        : "r"(a[0]), "r"(a[1]), "r"(a[2]), "r"(a[3]), "r"(b0), "r"(b1));
}
__device__ __forceinline__ void red_add_v4(float* p, float a, float b, float c, float d) {
    asm volatile("red.global.add.v4.f32 [%0], {%1, %2, %3, %4};"
        :: "l"(p), "f"(a), "f"(b), "f"(c), "f"(d) : "memory");
}
__device__ __forceinline__ void cp16(uint32_t d, const void* s) {
    asm volatile("cp.async.cg.shared.global [%0], [%1], 16;" :: "r"(d), "l"(s));
}
#define CP_COMMIT() asm volatile("cp.async.commit_group;" ::: "memory")
#define CP_WAIT0()  asm volatile("cp.async.wait_group 0;"  ::: "memory")

__device__ __host__ __forceinline__ int fperm(int n) {
    int wg = n >> 5, w = n & 31, q = w >> 3, tt = (w >> 1) & 3, r = w & 1;
    return wg * 32 + tt * 8 + q * 2 + r;
}

template<int AS, int BS>
__device__ __forceinline__ void gemm_step1(float (&c)[2][4][4],
    uint32_t aHi, uint32_t bHi, int akb, int bkb, int wm, int wn, int lane)
{
    const int rs = lane & 15;
    const int hs = (lane >> 4) << 4;
    uint32_t ah[2][4], bh[2][4];
    #pragma unroll
    for (int mt = 0; mt < 2; ++mt)
        ldsm4(ah[mt], aHi + (wm * 32 + mt * 16 + rs) * AS + akb + hs);
    #pragma unroll
    for (int nt = 0; nt < 2; ++nt)
        ldsm4(bh[nt], bHi + (wn * 32 + nt * 16 + rs) * BS + bkb + hs);
    #pragma unroll
    for (int mt = 0; mt < 2; ++mt)
        #pragma unroll
        for (int nt = 0; nt < 2; ++nt) {
            mma16816(c[mt][2 * nt],     ah[mt], bh[nt][0], bh[nt][2]);
            mma16816(c[mt][2 * nt + 1], ah[mt], bh[nt][1], bh[nt][3]);
        }
}

template<int AS, int BS>
__device__ __forceinline__ void gemm_stepA2(float (&c)[2][4][4],
    uint32_t aHi, uint32_t aLo, uint32_t bHi,
    int akb, int bkb, int wm, int wn, int lane)
{
    const int rs = lane & 15;
    const int hs = (lane >> 4) << 4;
    uint32_t ah[2][4], al[2][4], bh[2][4];
    #pragma unroll
    for (int mt = 0; mt < 2; ++mt) {
        ldsm4(ah[mt], aHi + (wm * 32 + mt * 16 + rs) * AS + akb + hs);
        ldsm4(al[mt], aLo + (wm * 32 + mt * 16 + rs) * AS + akb + hs);
    }
    #pragma unroll
    for (int nt = 0; nt < 2; ++nt)
        ldsm4(bh[nt], bHi + (wn * 32 + nt * 16 + rs) * BS + bkb + hs);
    #pragma unroll
    for (int mt = 0; mt < 2; ++mt)
        #pragma unroll
        for (int nt = 0; nt < 2; ++nt) {
            mma16816(c[mt][2 * nt],     ah[mt], bh[nt][0], bh[nt][2]);
            mma16816(c[mt][2 * nt + 1], ah[mt], bh[nt][1], bh[nt][3]);
            mma16816(c[mt][2 * nt],     al[mt], bh[nt][0], bh[nt][2]);
            mma16816(c[mt][2 * nt + 1], al[mt], bh[nt][1], bh[nt][3]);
        }
}

template<int AS, int BS>
__device__ __forceinline__ void gemm_step3(float (&c)[2][4][4],
    uint32_t aHi, uint32_t aLo, uint32_t bHi, uint32_t bLo,
    int akb, int bkb, int wm, int wn, int lane)
{
    const int rs = lane & 15;
    const int hs = (lane >> 4) << 4;
    uint32_t ah[2][4], al[2][4], bh[2][4], bl[2][4];
    #pragma unroll
    for (int mt = 0; mt < 2; ++mt) {
        ldsm4(ah[mt], aHi + (wm * 32 + mt * 16 + rs) * AS + akb + hs);
        ldsm4(al[mt], aLo + (wm * 32 + mt * 16 + rs) * AS + akb + hs);
    }
    #pragma unroll
    for (int nt = 0; nt < 2; ++nt) {
        ldsm4(bh[nt], bHi + (wn * 32 + nt * 16 + rs) * BS + bkb + hs);
        ldsm4(bl[nt], bLo + (wn * 32 + nt * 16 + rs) * BS + bkb + hs);
    }
    #pragma unroll
    for (int mt = 0; mt < 2; ++mt)
        #pragma unroll
        for (int nt = 0; nt < 2; ++nt) {
            mma16816(c[mt][2 * nt],     ah[mt], bh[nt][0], bh[nt][2]);
            mma16816(c[mt][2 * nt + 1], ah[mt], bh[nt][1], bh[nt][3]);
            mma16816(c[mt][2 * nt],     ah[mt], bl[nt][0], bl[nt][2]);
            mma16816(c[mt][2 * nt + 1], ah[mt], bl[nt][1], bl[nt][3]);
            mma16816(c[mt][2 * nt],     al[mt], bh[nt][0], bh[nt][2]);
            mma16816(c[mt][2 * nt + 1], al[mt], bh[nt][1], bh[nt][3]);
        }
}

__device__ __forceinline__ void splitpack8(float4 v0, float4 v1, uint4& hi, uint4& lo) {
    float f[8] = {v0.x, v0.y, v0.z, v0.w, v1.x, v1.y, v1.z, v1.w};
    uint32_t hw[4], lw[4];
    #pragma unroll
    for (int j = 0; j < 4; ++j) {
        __half h0 = __float2half_rn(f[2 * j]), h1 = __float2half_rn(f[2 * j + 1]);
        hw[j] = packh2(h0, h1);
        lw[j] = packh2(__float2half_rn(f[2 * j] - __half2float(h0)),
                       __float2half_rn(f[2 * j + 1] - __half2float(h1)));
    }
    hi = make_uint4(hw[0], hw[1], hw[2], hw[3]);
    lo = make_uint4(lw[0], lw[1], lw[2], lw[3]);
}

// ---------------- merged prologue kernel ----------------
__global__ void prep_kernel(const float* __restrict__ nf,
                            const float* __restrict__ mw1, const float* __restrict__ mw2,
                            const float* __restrict__ mb2,
                            const float* __restrict__ uw1, const float* __restrict__ uw2,
                            const void* __restrict__ ei, int N, int E)
{
    const int gs = gridDim.x * blockDim.x;
    const int g0 = blockIdx.x * blockDim.x + threadIdx.x;

    for (int t = g0; t < 73728; t += gs) {
        int u = t;
        if (u < 16384) {                      // W1Ma
            int n = u >> 7, k = u & 127;
            g_wimg[HW_W1MA + fperm(n) * 136 + k] = __float2half_rn(mw1[(size_t)k * 128 + n]);
        } else if (u < 24576) {               // W1Mb
            u -= 16384; int n = u >> 6, k = u & 63;
            g_wimg[HW_W1MB + fperm(n) * 72 + k] = __float2half_rn(mw1[(size_t)(128 + k) * 128 + n]);
        } else if (u < 57344) {               // W1U (k<128) + chain Wc (k>=128)
            u -= 24576; int n = u >> 8, k = u & 255;
            float v;
            if (k < 128) {
                v = uw1[(size_t)k * 128 + n];
            } else {
                int kk = k - 128;
                v = 0.f;
                for (int j = 0; j < 128; ++j)
                    v += mw2[(size_t)kk * 128 + j] * uw1[(size_t)(128 + j) * 128 + n];
            }
            g_wimg[HW_W1U + n * 264 + k] = __float2half_rn(v);
        } else {                              // W2U hi+lo
            u -= 57344; int n = u >> 7, k = u & 127;
            float v = uw2[(size_t)k * 128 + n];
            __half h = __float2half_rn(v);
            int row = fperm(n);
            g_wimg[HW_W2UH + row * 136 + k] = h;
            g_wimg[HW_W2UL + row * 136 + k] = __float2half_rn(v - __half2float(h));
        }
    }
    for (int t = g0; t < 128; t += gs) {
        float v = 0.f;
        for (int j = 0; j < 128; ++j)
            v += mb2[j] * uw1[(size_t)(128 + j) * 128 + t];
        g_vc[t] = v;
    }
    for (int i = g0; i < N * 64; i += gs) {
        float2 v = ((const float2*)nf)[i];
        __half h0 = __float2half_rn(v.x), h1 = __float2half_rn(v.y);
        ((uint32_t*)g_nfh)[i] = packh2(h0, h1);
        ((uint32_t*)g_nfl)[i] = packh2(__float2half_rn(v.x - __half2float(h0)),
                                       __float2half_rn(v.y - __half2float(h1)));
    }
    {
        const int* p32 = (const int*)ei;
        int s = 0;
        #pragma unroll
        for (int i = 0; i < 16; ++i) s |= p32[2 * i + 1];
        if (s == 0) {
            const long long* p = (const long long*)ei;
            for (int i = g0; i < E; i += gs) {
                g_src[i] = (int)p[i];
                g_dst[i] = (int)p[(size_t)E + i];
            }
        } else {
            for (int i = g0; i < E; i += gs) {
                g_src[i] = p32[i];
                g_dst[i] = p32[(size_t)E + i];
            }
        }
    }
    {
        float4 z = make_float4(0.f, 0.f, 0.f, 0.f);
        for (int i = g0; i < N * 32; i += gs) ((float4*)g_agg)[i] = z;
        for (int i = g0; i < N; i += gs) g_cnt[i] = 0;
    }
}

// ---------------- sort kernels ----------------
__global__ void hist_kernel(int E) {
    int gs = gridDim.x * blockDim.x;
    for (int i = blockIdx.x * blockDim.x + threadIdx.x; i < E; i += gs)
        atomicAdd(&g_cnt[g_src[i]], 1);
}

__global__ void scan_kernel(int N) {   // single block, 1024 threads
    __shared__ int ssum[1024];
    int tid = threadIdx.x;
    int chunk = (N + 1023) / 1024;
    int lo = tid * chunk, hi = lo + chunk;
    if (hi > N) hi = N;
    int s = 0;
    for (int i = lo; i < hi; ++i) s += g_cnt[i];
    ssum[tid] = s;
    __syncthreads();
    for (int d = 1; d < 1024; d <<= 1) {
        int v = (tid >= d) ? ssum[tid - d] : 0;
        __syncthreads();
        ssum[tid] += v;
        __syncthreads();
    }
    int run = (tid > 0) ? ssum[tid - 1] : 0;
    for (int i = lo; i < hi; ++i) {
        g_pos[i] = run;
        run += g_cnt[i];
    }
}

__global__ void scatter_kernel(int E) {
    int gs = gridDim.x * blockDim.x;
    for (int i = blockIdx.x * blockDim.x + threadIdx.x; i < E; i += gs) {
        int s = g_src[i];
        int p = atomicAdd(&g_pos[s], 1);
        g_ssrc[p] = s;
        g_sdst[p] = g_dst[i];
        g_seid[p] = i;
    }
}

// ---------------- P kernel: g_Ph = fp16(nf @ W1a + b1) ----------------
#define Q_W1  0
#define Q_XH  34816
#define Q_XL  69632
#define Q_B1  104448
#define Q_DYN 104960

__global__ __launch_bounds__(512, 1)
void pmat_kernel(const float* __restrict__ b1g, int N, int nTiles)
{
    extern __shared__ char smx[];
    const uint32_t sb = smem_u32(smx);
    float* sb1 = (float*)(smx + Q_B1);
    const int tid = threadIdx.x, lane = tid & 31, wid = tid >> 5;
    const int wm = wid & 3, wn = wid >> 2;

    if (tid < 128) sb1[tid] = b1g[tid];
    {
        const uint4* s = (const uint4*)((const char*)g_wimg + BW_W1MA);
        uint4* d = (uint4*)(smx + Q_W1);
        for (int i = tid; i < 2176; i += 512) d[i] = s[i];
    }

    for (int tile = blockIdx.x; tile < nTiles; tile += gridDim.x) {
        const int n0 = tile * 128;
        __syncthreads();
        for (int t = tid; t < 128 * 32; t += 512) {
            int row = t >> 5, ch = t & 31;
            int n = n0 + row; if (n >= N) n = N - 1;
            if (ch < 16)
                *(uint4*)(smx + Q_XH + row * 272 + ch * 16) = ((const uint4*)(g_nfh + (size_t)n * 128))[ch];
            else
                *(uint4*)(smx + Q_XL + row * 272 + (ch - 16) * 16) = ((const uint4*)(g_nfl + (size_t)n * 128))[ch - 16];
        }
        __syncthreads();

        float c[2][4][4];
        #pragma unroll
        for (int i = 0; i < 2; ++i)
            #pragma unroll
            for (int j = 0; j < 4; ++j)
                #pragma unroll
                for (int r = 0; r < 4; ++r) c[i][j][r] = 0.f;
        #pragma unroll
        for (int k = 0; k < 8; ++k)
            gemm_stepA2<272, 272>(c, sb + Q_XH, sb + Q_XL, sb + Q_W1,
                                  k * 32, k * 32, wm, wn, lane);

        const int q = lane & 3;
        const int Lb = wn * 32 + q * 8;
        float b0 = sb1[Lb],      b1v = sb1[Lb + 1], b2v = sb1[Lb + 2], b3v = sb1[Lb + 3];
        float b4v = sb1[Lb + 4], b5v = sb1[Lb + 5], b6v = sb1[Lb + 6], b7v = sb1[Lb + 7];
        #pragma unroll
        for (int mt = 0; mt < 2; ++mt) {
            int r = wm * 32 + mt * 16 + (lane >> 2);
            int nA = n0 + r, nB = n0 + r + 8;
            if (nA < N) {
                *(uint4*)(g_Ph + (size_t)nA * 128 + Lb) = make_uint4(
                    packh2(__float2half_rn(c[mt][0][0] + b0),  __float2half_rn(c[mt][0][1] + b1v)),
                    packh2(__float2half_rn(c[mt][1][0] + b2v), __float2half_rn(c[mt][1][1] + b3v)),
                    packh2(__float2half_rn(c[mt][2][0] + b4v), __float2half_rn(c[mt][2][1] + b5v)),
                    packh2(__float2half_rn(c[mt][3][0] + b6v), __float2half_rn(c[mt][3][1] + b7v)));
            }
            if (nB < N) {
                *(uint4*)(g_Ph + (size_t)nB * 128 + Lb) = make_uint4(
                    packh2(__float2half_rn(c[mt][0][2] + b0),  __float2half_rn(c[mt][0][3] + b1v)),
                    packh2(__float2half_rn(c[mt][1][2] + b2v), __float2half_rn(c[mt][1][3] + b3v)),
                    packh2(__float2half_rn(c[mt][2][2] + b4v), __float2half_rn(c[mt][2][3] + b5v)),
                    packh2(__float2half_rn(c[mt][3][2] + b6v), __float2half_rn(c[mt][3][3] + b7v)));
            }
        }
    }
}

// ---------------- edge kernel smem layout (bytes) ----------------
#define E_W1B 0        // W1Mb hi 18432 (stride 144)
#define E_X   18432    // X (ef fp16) 128x144 = 18432
#define E_EF  36864    // fp32 ef staging 128x256 = 32768
#define E_P0  69632    // P fp16 buf0 128x272 = 34816
#define E_P1  104448   // P fp16 buf1
#define E_HB  139264   // H fp32 buf 128x132x4 = 67584
#define E_SRC 206848   // [2][128]
#define E_DYN 207872

__device__ __forceinline__ void issue_gather(char* smx, int buf, int tile, int E, int tid,
                                             const float* __restrict__ ef) {
    const uint32_t sf = smem_u32(smx) + E_EF;
    const uint32_t pb = smem_u32(smx) + (buf ? E_P1 : E_P0);
    const int e0 = tile * 128;
    #pragma unroll
    for (int j = 0; j < 8; ++j) {
        int t = tid + j * 512;            // 0..4095
        int row = t >> 5, ch = t & 31;
        int e = e0 + row; if (e >= E) e = E - 1;
        if (ch < 16) {
            int eid = g_seid[e];
            cp16(sf + row * 256 + ch * 16, ef + (size_t)eid * 64 + ch * 4);
        } else {
            int dn = g_sdst[e];
            cp16(pb + row * 272 + (ch - 16) * 16, g_Ph + (size_t)dn * 128 + (ch - 16) * 8);
        }
    }
}

__global__ __launch_bounds__(512, 1)
void edge_mma_kernel(const float* __restrict__ edge_feats, int E, int nTiles)
{
    extern __shared__ char smx[];
    const uint32_t sb = smem_u32(smx);
    int* s_src = (int*)(smx + E_SRC);
    const int tid = threadIdx.x, lane = tid & 31, wid = tid >> 5;
    const int wm = wid & 3, wn = wid >> 2;

    {
        const uint4* s1 = (const uint4*)((const char*)g_wimg + BW_W1MB);
        uint4* d1 = (uint4*)(smx + E_W1B);
        for (int i = tid; i < 1152; i += 512) d1[i] = s1[i];
    }

    int tile = blockIdx.x;
    if (tile < nTiles) {
        issue_gather(smx, 0, tile, E, tid, edge_feats);
        if (tid < 128) {
            int e = tile * 128 + tid;
            s_src[tid] = (e < E) ? g_ssrc[e] : -1;
        }
    }
    CP_COMMIT();

    int b = 0;
    for (; tile < nTiles; tile += gridDim.x, b ^= 1) {
        CP_WAIT0();
        __syncthreads();     // staging + P[b] + s_src[b] ready; prev tile fully done

        // convert fp32 ef staging -> fp16 X (stride 144)
        for (int t = tid; t < 1024; t += 512) {
            int row = t >> 3, q = t & 7;
            const float4* sp = (const float4*)(smx + E_EF + row * 256 + q * 32);
            float4 v0 = sp[0], v1 = sp[1];
            *(uint4*)(smx + E_X + row * 144 + q * 16) = make_uint4(
                packh2(__float2half_rn(v0.x), __float2half_rn(v0.y)),
                packh2(__float2half_rn(v0.z), __float2half_rn(v0.w)),
                packh2(__float2half_rn(v1.x), __float2half_rn(v1.y)),
                packh2(__float2half_rn(v1.z), __float2half_rn(v1.w)));
        }
        __syncthreads();     // staging consumed

        int nextTile = tile + gridDim.x;
        if (nextTile < nTiles) {
            issue_gather(smx, b ^ 1, nextTile, E, tid, edge_feats);
            if (tid < 128) {
                int e = nextTile * 128 + tid;
                s_src[(b ^ 1) * 128 + tid] = (e < E) ? g_ssrc[e] : -1;
            }
        }
        CP_COMMIT();

        // GEMM1: K=64, 1-term (ef @ W1b)
        float c[2][4][4];
        #pragma unroll
        for (int i = 0; i < 2; ++i)
            #pragma unroll
            for (int j = 0; j < 4; ++j)
                #pragma unroll
                for (int r = 0; r < 4; ++r) c[i][j][r] = 0.f;
        #pragma unroll
        for (int k = 0; k < 4; ++k)
            gemm_step1<144, 144>(c, sb + E_X, sb + E_W1B, k * 32, k * 32, wm, wn, lane);

        // phase1: H = lrelu(c + P[b]) -> fp32 smem Hbuf (stride 132 floats)
        {
            const int q = lane & 3;
            const int Lb = wn * 32 + q * 8;
            char* pbuf = smx + (b ? E_P1 : E_P0);
            #pragma unroll
            for (int mt = 0; mt < 2; ++mt) {
                int r = wm * 32 + mt * 16 + (lane >> 2);
                uint4 pa = *(uint4*)(pbuf + r * 272 + Lb * 2);
                uint4 pbv = *(uint4*)(pbuf + (r + 8) * 272 + Lb * 2);
                float2 a0 = unp2(pa.x), a1 = unp2(pa.y), a2 = unp2(pa.z), a3 = unp2(pa.w);
                float* hb0 = (float*)(smx + E_HB) + r * 132 + Lb;
                ((float4*)hb0)[0] = make_float4(
                    lrelu(c[mt][0][0] + a0.x), lrelu(c[mt][0][1] + a0.y),
                    lrelu(c[mt][1][0] + a1.x), lrelu(c[mt][1][1] + a1.y));
                ((float4*)hb0)[1] = make_float4(
                    lrelu(c[mt][2][0] + a2.x), lrelu(c[mt][2][1] + a2.y),
                    lrelu(c[mt][3][0] + a3.x), lrelu(c[mt][3][1] + a3.y));
                float2 b0 = unp2(pbv.x), b1 = unp2(pbv.y), b2 = unp2(pbv.z), b3 = unp2(pbv.w);
                float* hb1 = (float*)(smx + E_HB) + (r + 8) * 132 + Lb;
                ((float4*)hb1)[0] = make_float4(
                    lrelu(c[mt][0][2] + b0.x), lrelu(c[mt][0][3] + b0.y),
                    lrelu(c[mt][1][2] + b1.x), lrelu(c[mt][1][3] + b1.y));
                ((float4*)hb1)[1] = make_float4(
                    lrelu(c[mt][2][2] + b2.x), lrelu(c[mt][2][3] + b2.y),
                    lrelu(c[mt][3][2] + b3.x), lrelu(c[mt][3][3] + b3.y));
            }
        }
        __syncthreads();     // Hbuf complete

        // phase2: segmented reduction over sorted src runs, flush red.v4
        {
            const int cg = tid & 31;          // col group: cols 4cg..4cg+3
            const int rbase = (tid >> 5) * 8; // 16 chunks x 8 rows
            const int* sp = s_src + b * 128;
            const float* hb = (const float*)(smx + E_HB);
            float4 acc = make_float4(0.f, 0.f, 0.f, 0.f);
            int cur = sp[rbase];
            #pragma unroll
            for (int i = 0; i < 8; ++i) {
                int r = rbase + i;
                int s = sp[r];
                if (s != cur) {
                    if (cur >= 0)
                        red_add_v4(g_agg + (size_t)cur * 128 + cg * 4, acc.x, acc.y, acc.z, acc.w);
                    acc = make_float4(0.f, 0.f, 0.f, 0.f);
                    cur = s;
                }
                float4 h = ((const float4*)(hb + r * 132 + cg * 4))[0];
                acc.x += h.x; acc.y += h.y; acc.z += h.z; acc.w += h.w;
            }
            if (cur >= 0)
                red_add_v4(g_agg + (size_t)cur * 128 + cg * 4, acc.x, acc.y, acc.z, acc.w);
        }
    }
}

// ---------------- persistent node kernel smem layout (bytes) ----------------
#define P_W1  0        // W1U hi (k>=128 rows = Wc), stride 528, 67584
#define P_W2H 67584
#define P_W2L 102400
#define P_XH  137216
#define P_XL  172032
#define P_SB1 206848
#define P_SB2 207360
#define P_VC  207872
#define P_DEG 208384
#define P_DYN 208896

__global__ __launch_bounds__(512, 1)
void node_mma_kernel(const float* __restrict__ b1g, const float* __restrict__ b2g,
                     float* __restrict__ out, int N, int nTiles)
{
    extern __shared__ char smx[];
    const uint32_t sb = smem_u32(smx);
    float* sb1  = (float*)(smx + P_SB1);
    float* sb2  = (float*)(smx + P_SB2);
    float* svc  = (float*)(smx + P_VC);
    float* sdeg = (float*)(smx + P_DEG);
    const int tid = threadIdx.x, lane = tid & 31, wid = tid >> 5;
    const int wm = wid & 3, wn = wid >> 2;

    if (tid < 128)      sb1[tid] = b1g[tid];
    else if (tid < 256) sb2[tid - 128] = b2g[tid - 128];
    else if (tid < 384) svc[tid - 256] = g_vc[tid - 256];
    {
        const uint4* s1 = (const uint4*)((const char*)g_wimg + BW_W1U);
        uint4* d1 = (uint4*)(smx + P_W1);
        for (int i = tid; i < 4224; i += 512) d1[i] = s1[i];
        const uint4* s2 = (const uint4*)((const char*)g_wimg + BW_W2U);
        uint4* d2 = (uint4*)(smx + P_W2H);
        for (int i = tid; i < 4352; i += 512) d2[i] = s2[i];
    }

    for (int tile = blockIdx.x; tile < nTiles; tile += gridDim.x) {
        const int n0 = tile * 128;
        __syncthreads();

        for (int t = tid; t < 128 * 32; t += 512) {
            int row = t >> 5, ch = t & 31;
            int n = n0 + row; if (n >= N) n = N - 1;
            if (ch < 16)
                *(uint4*)(smx + P_XH + row * 272 + ch * 16) = ((const uint4*)(g_nfh + (size_t)n * 128))[ch];
            else
                *(uint4*)(smx + P_XL + row * 272 + (ch - 16) * 16) = ((const uint4*)(g_nfl + (size_t)n * 128))[ch - 16];
        }
        if (tid < 128) {
            int n = n0 + tid;
            sdeg[tid] = (n < N) ? (float)g_cnt[n] : 0.f;
        }
        __syncthreads();

        float c[2][4][4];
        #pragma unroll
        for (int i = 0; i < 2; ++i)
            #pragma unroll
            for (int j = 0; j < 4; ++j)
                #pragma unroll
                for (int r = 0; r < 4; ++r) c[i][j][r] = 0.f;
        #pragma unroll
        for (int k = 0; k < 8; ++k)
            gemm_stepA2<272, 528>(c, sb + P_XH, sb + P_XL, sb + P_W1,
                                  k * 32, k * 32, wm, wn, lane);
        __syncthreads();

        for (int t = tid; t < 128 * 16; t += 512) {
            int row = t >> 4, ch = t & 15;
            int n = n0 + row; if (n >= N) n = N - 1;
            const float4* bp = (const float4*)(g_agg + (size_t)n * 128 + ch * 8);
            uint4 hi, lo;
            splitpack8(bp[0], bp[1], hi, lo);
            *(uint4*)(smx + P_XH + row * 272 + ch * 16) = hi;
            *(uint4*)(smx + P_XL + row * 272 + ch * 16) = lo;
        }
        __syncthreads();
        #pragma unroll
        for (int k = 0; k < 8; ++k)
            gemm_stepA2<272, 528>(c, sb + P_XH, sb + P_XL, sb + P_W1,
                                  k * 32, 256 + k * 32, wm, wn, lane);
        __syncthreads();

        #pragma unroll
        for (int mt = 0; mt < 2; ++mt)
            #pragma unroll
            for (int nt = 0; nt < 4; ++nt) {
                int r0  = wm * 32 + mt * 16 + (lane >> 2);
                int col = wn * 32 + nt * 8 + (lane & 3) * 2;
                float dA = sdeg[r0], dB = sdeg[r0 + 8];
                float vca = svc[col], vcb = svc[col + 1];
                float ba = sb1[col], bb = sb1[col + 1];
                float f0 = lrelu(c[mt][nt][0] + ba + dA * vca), f1 = lrelu(c[mt][nt][1] + bb + dA * vcb);
                float f2 = lrelu(c[mt][nt][2] + ba + dB * vca), f3 = lrelu(c[mt][nt][3] + bb + dB * vcb);
                __half h0 = __float2half_rn(f0), h1 = __float2half_rn(f1);
                __half h2 = __float2half_rn(f2), h3 = __float2half_rn(f3);
                *(uint32_t*)(smx + P_XH + r0 * 272 + col * 2)       = packh2(h0, h1);
                *(uint32_t*)(smx + P_XH + (r0 + 8) * 272 + col * 2) = packh2(h2, h3);
                *(uint32_t*)(smx + P_XL + r0 * 272 + col * 2) =
                    packh2(__float2half_rn(f0 - __half2float(h0)), __float2half_rn(f1 - __half2float(h1)));
                *(uint32_t*)(smx + P_XL + (r0 + 8) * 272 + col * 2) =
                    packh2(__float2half_rn(f2 - __half2float(h2)), __float2half_rn(f3 - __half2float(h3)));
            }
        __syncthreads();

        #pragma unroll
        for (int i = 0; i < 2; ++i)
            #pragma unroll
            for (int j = 0; j < 4; ++j)
                #pragma unroll
                for (int r = 0; r < 4; ++r) c[i][j][r] = 0.f;
        #pragma unroll
        for (int k = 0; k < 8; ++k)
            gemm_step3<272, 272>(c, sb + P_XH, sb + P_XL, sb + P_W2H, sb + P_W2L,
                                 k * 32, k * 32, wm, wn, lane);

        {
            const int q = lane & 3;
            const int Lb = wn * 32 + q * 8;
            float c0 = sb2[Lb],     c1 = sb2[Lb + 1], c2 = sb2[Lb + 2], c3 = sb2[Lb + 3];
            float c4 = sb2[Lb + 4], c5 = sb2[Lb + 5], c6 = sb2[Lb + 6], c7 = sb2[Lb + 7];
            #pragma unroll
            for (int mt = 0; mt < 2; ++mt) {
                int r = wm * 32 + mt * 16 + (lane >> 2);
                int nA = n0 + r, nB = n0 + r + 8;
                if (nA < N) {
                    float4* p = (float4*)(out + (size_t)nA * 128 + Lb);
                    p[0] = make_float4(c[mt][0][0] + c0, c[mt][0][1] + c1, c[mt][1][0] + c2, c[mt][1][1] + c3);
                    p[1] = make_float4(c[mt][2][0] + c4, c[mt][2][1] + c5, c[mt][3][0] + c6, c[mt][3][1] + c7);
                }
                if (nB < N) {
                    float4* p = (float4*)(out + (size_t)nB * 128 + Lb);
                    p[0] = make_float4(c[mt][0][2] + c0, c[mt][0][3] + c1, c[mt][1][2] + c2, c[mt][1][3] + c3);
                    p[1] = make_float4(c[mt][2][2] + c4, c[mt][2][3] + c5, c[mt][3][2] + c6, c[mt][3][3] + c7);
                }
            }
        }
    }
}

// ---------------------------------------------------------------------------

extern "C" void kernel_launch(void* const* d_in, const int* in_sizes, int n_in,
                              void* d_out, int out_size)
{
    const float* node_feats = (const float*)d_in[0];
    const float* edge_feats = (const float*)d_in[1];
    const float* msg_w1     = (const float*)d_in[2];
    const float* msg_b1     = (const float*)d_in[3];
    const float* msg_w2     = (const float*)d_in[4];
    const float* msg_b2     = (const float*)d_in[5];
    const float* upd_w1     = (const float*)d_in[6];
    const float* upd_b1     = (const float*)d_in[7];
    const float* upd_w2     = (const float*)d_in[8];
    const float* upd_b2     = (const float*)d_in[9];
    const void*  edge_index = d_in[10];

    const int N = in_sizes[0] / 128;   // 50000
    const int E = in_sizes[1] / 64;    // 800000
    const int nTiles  = (E + 127) / 128;
    const int nNTiles = (N + 127) / 128;

    cudaFuncSetAttribute(pmat_kernel,     cudaFuncAttributeMaxDynamicSharedMemorySize, Q_DYN);
    cudaFuncSetAttribute(edge_mma_kernel, cudaFuncAttributeMaxDynamicSharedMemorySize, E_DYN);
    cudaFuncSetAttribute(node_mma_kernel, cudaFuncAttributeMaxDynamicSharedMemorySize, P_DYN);

    prep_kernel<<<1024, 256>>>(node_feats, msg_w1, msg_w2, msg_b2,
                               upd_w1, upd_w2, edge_index, N, E);

    hist_kernel<<<400, 256>>>(E);
    scan_kernel<<<1, 1024>>>(N);
    scatter_kernel<<<400, 256>>>(E);

    pmat_kernel<<<148, 512, Q_DYN>>>(msg_b1, N, nNTiles);

    edge_mma_kernel<<<148, 512, E_DYN>>>(edge_feats, E, nTiles);

    node_mma_kernel<<<148, 512, P_DYN>>>(upd_b1, upd_b2, (float*)d_out, N, nNTiles);
}

// round 16
// speedup vs baseline: 1.2085x; 1.2085x over previous
#include <cuda_runtime.h>
#include <cuda_fp16.h>
#include <cstdint>

// ===========================================================================
// GraphConvLayer, v10: R14 structure (linear-scatter factoring, unsorted)
// with a 2-blocks/SM edge kernel: smem cut to 105 KB, P single-buffered and
// fetched via a second cp.async group that overlaps GEMM1.
// ===========================================================================

#define MAX_N 50000
#define MAX_E 800000

__device__ float  g_agg[(size_t)MAX_N * 128];
__device__ float  g_degf[MAX_N];
__device__ float  g_vc[128];
__device__ __half g_Ph[(size_t)MAX_N * 128];
__device__ int    g_src[MAX_E];
__device__ int    g_dst[MAX_E];
__device__ __half g_nfh[(size_t)MAX_N * 128];
__device__ __half g_nfl[(size_t)MAX_N * 128];
// weight images: W1Ma hi(perm,136) W1Mb hi(perm,72) W1U hi(264, k>=128 = Wc) W2U hi/lo(perm,136)
__device__ __half g_wimg[112640];

#define HW_W1MA 0
#define HW_W1MB 17408
#define HW_W1U  26624
#define HW_W2UH 60416
#define HW_W2UL 77824
#define BW_W1MA 0
#define BW_W1MB 34816
#define BW_W1U  53248
#define BW_W2U  120832   // hi+lo contiguous 69632

// ---------------- helpers ----------------
__device__ __forceinline__ uint32_t smem_u32(const void* p) {
    uint32_t a;
    asm("{ .reg .u64 t; cvta.to.shared.u64 t, %1; cvt.u32.u64 %0, t; }" : "=r"(a) : "l"(p));
    return a;
}
__device__ __forceinline__ float lrelu(float v) { return v >= 0.f ? v : 0.2f * v; }
__device__ __forceinline__ uint32_t packh2(__half a, __half b) {
    __half2 h = __halves2half2(a, b);
    return *reinterpret_cast<uint32_t*>(&h);
}
__device__ __forceinline__ float2 unp2(uint32_t u) {
    __half2 h = *reinterpret_cast<__half2*>(&u);
    return __half22float2(h);
}
__device__ __forceinline__ void ldsm4(uint32_t* r, uint32_t a) {
    asm volatile("ldmatrix.sync.aligned.m8n8.x4.shared.b16 {%0,%1,%2,%3}, [%4];"
        : "=r"(r[0]), "=r"(r[1]), "=r"(r[2]), "=r"(r[3]) : "r"(a));
}
__device__ __forceinline__ void mma16816(float* c, const uint32_t* a, uint32_t b0, uint32_t b1) {
    asm volatile("mma.sync.aligned.m16n8k16.row.col.f32.f16.f16.f32 "
        "{%0,%1,%2,%3}, {%4,%5,%6,%7}, {%8,%9}, {%0,%1,%2,%3};"
        : "+f"(c[0]), "+f"(c[1]), "+f"(c[2]), "+f"(c[3])
        : "r"(a[0]), "r"(a[1]), "r"(a[2]), "r"(a[3]), "r"(b0), "r"(b1));
}
__device__ __forceinline__ void red_add_v4(float* p, float a, float b, float c, float d) {
    asm volatile("red.global.add.v4.f32 [%0], {%1, %2, %3, %4};"
        :: "l"(p), "f"(a), "f"(b), "f"(c), "f"(d) : "memory");
}
__device__ __forceinline__ void red_add_f(float* p, float v) {
    asm volatile("red.global.add.f32 [%0], %1;" :: "l"(p), "f"(v) : "memory");
}
__device__ __forceinline__ void cp16(uint32_t d, const void* s) {
    asm volatile("cp.async.cg.shared.global [%0], [%1], 16;" :: "r"(d), "l"(s));
}
#define CP_COMMIT() asm volatile("cp.async.commit_group;" ::: "memory")
#define CP_WAIT0()  asm volatile("cp.async.wait_group 0;"  ::: "memory")
#define CP_WAIT1()  asm volatile("cp.async.wait_group 1;"  ::: "memory")

__device__ __host__ __forceinline__ int fperm(int n) {
    int wg = n >> 5, w = n & 31, q = w >> 3, tt = (w >> 1) & 3, r = w & 1;
    return wg * 32 + tt * 8 + q * 2 + r;
}

template<int AS, int BS>
__device__ __forceinline__ void gemm_step1(float (&c)[2][4][4],
    uint32_t aHi, uint32_t bHi, int akb, int bkb, int wm, int wn, int lane)
{
    const int rs = lane & 15;
    const int hs = (lane >> 4) << 4;
    uint32_t ah[2][4], bh[2][4];
    #pragma unroll
    for (int mt = 0; mt < 2; ++mt)
        ldsm4(ah[mt], aHi + (wm * 32 + mt * 16 + rs) * AS + akb + hs);
    #pragma unroll
    for (int nt = 0; nt < 2; ++nt)
        ldsm4(bh[nt], bHi + (wn * 32 + nt * 16 + rs) * BS + bkb + hs);
    #pragma unroll
    for (int mt = 0; mt < 2; ++mt)
        #pragma unroll
        for (int nt = 0; nt < 2; ++nt) {
            mma16816(c[mt][2 * nt],     ah[mt], bh[nt][0], bh[nt][2]);
            mma16816(c[mt][2 * nt + 1], ah[mt], bh[nt][1], bh[nt][3]);
        }
}

template<int AS, int BS>
__device__ __forceinline__ void gemm_stepA2(float (&c)[2][4][4],
    uint32_t aHi, uint32_t aLo, uint32_t bHi,
    int akb, int bkb, int wm, int wn, int lane)
{
    const int rs = lane & 15;
    const int hs = (lane >> 4) << 4;
    uint32_t ah[2][4], al[2][4], bh[2][4];
    #pragma unroll
    for (int mt = 0; mt < 2; ++mt) {
        ldsm4(ah[mt], aHi + (wm * 32 + mt * 16 + rs) * AS + akb + hs);
        ldsm4(al[mt], aLo + (wm * 32 + mt * 16 + rs) * AS + akb + hs);
    }
    #pragma unroll
    for (int nt = 0; nt < 2; ++nt)
        ldsm4(bh[nt], bHi + (wn * 32 + nt * 16 + rs) * BS + bkb + hs);
    #pragma unroll
    for (int mt = 0; mt < 2; ++mt)
        #pragma unroll
        for (int nt = 0; nt < 2; ++nt) {
            mma16816(c[mt][2 * nt],     ah[mt], bh[nt][0], bh[nt][2]);
            mma16816(c[mt][2 * nt + 1], ah[mt], bh[nt][1], bh[nt][3]);
            mma16816(c[mt][2 * nt],     al[mt], bh[nt][0], bh[nt][2]);
            mma16816(c[mt][2 * nt + 1], al[mt], bh[nt][1], bh[nt][3]);
        }
}

template<int AS, int BS>
__device__ __forceinline__ void gemm_step3(float (&c)[2][4][4],
    uint32_t aHi, uint32_t aLo, uint32_t bHi, uint32_t bLo,
    int akb, int bkb, int wm, int wn, int lane)
{
    const int rs = lane & 15;
    const int hs = (lane >> 4) << 4;
    uint32_t ah[2][4], al[2][4], bh[2][4], bl[2][4];
    #pragma unroll
    for (int mt = 0; mt < 2; ++mt) {
        ldsm4(ah[mt], aHi + (wm * 32 + mt * 16 + rs) * AS + akb + hs);
        ldsm4(al[mt], aLo + (wm * 32 + mt * 16 + rs) * AS + akb + hs);
    }
    #pragma unroll
    for (int nt = 0; nt < 2; ++nt) {
        ldsm4(bh[nt], bHi + (wn * 32 + nt * 16 + rs) * BS + bkb + hs);
        ldsm4(bl[nt], bLo + (wn * 32 + nt * 16 + rs) * BS + bkb + hs);
    }
    #pragma unroll
    for (int mt = 0; mt < 2; ++mt)
        #pragma unroll
        for (int nt = 0; nt < 2; ++nt) {
            mma16816(c[mt][2 * nt],     ah[mt], bh[nt][0], bh[nt][2]);
            mma16816(c[mt][2 * nt + 1], ah[mt], bh[nt][1], bh[nt][3]);
            mma16816(c[mt][2 * nt],     ah[mt], bl[nt][0], bl[nt][2]);
            mma16816(c[mt][2 * nt + 1], ah[mt], bl[nt][1], bl[nt][3]);
            mma16816(c[mt][2 * nt],     al[mt], bh[nt][0], bh[nt][2]);
            mma16816(c[mt][2 * nt + 1], al[mt], bh[nt][1], bh[nt][3]);
        }
}

__device__ __forceinline__ void splitpack8(float4 v0, float4 v1, uint4& hi, uint4& lo) {
    float f[8] = {v0.x, v0.y, v0.z, v0.w, v1.x, v1.y, v1.z, v1.w};
    uint32_t hw[4], lw[4];
    #pragma unroll
    for (int j = 0; j < 4; ++j) {
        __half h0 = __float2half_rn(f[2 * j]), h1 = __float2half_rn(f[2 * j + 1]);
        hw[j] = packh2(h0, h1);
        lw[j] = packh2(__float2half_rn(f[2 * j] - __half2float(h0)),
                       __float2half_rn(f[2 * j + 1] - __half2float(h1)));
    }
    hi = make_uint4(hw[0], hw[1], hw[2], hw[3]);
    lo = make_uint4(lw[0], lw[1], lw[2], lw[3]);
}

// ---------------- merged prologue kernel ----------------
__global__ void prep_kernel(const float* __restrict__ nf,
                            const float* __restrict__ mw1, const float* __restrict__ mw2,
                            const float* __restrict__ mb2,
                            const float* __restrict__ uw1, const float* __restrict__ uw2,
                            const void* __restrict__ ei, int N, int E)
{
    const int gs = gridDim.x * blockDim.x;
    const int g0 = blockIdx.x * blockDim.x + threadIdx.x;

    for (int t = g0; t < 73728; t += gs) {
        int u = t;
        if (u < 16384) {                      // W1Ma
            int n = u >> 7, k = u & 127;
            g_wimg[HW_W1MA + fperm(n) * 136 + k] = __float2half_rn(mw1[(size_t)k * 128 + n]);
        } else if (u < 24576) {               // W1Mb
            u -= 16384; int n = u >> 6, k = u & 63;
            g_wimg[HW_W1MB + fperm(n) * 72 + k] = __float2half_rn(mw1[(size_t)(128 + k) * 128 + n]);
        } else if (u < 57344) {               // W1U (k<128) + chain Wc (k>=128)
            u -= 24576; int n = u >> 8, k = u & 255;
            float v;
            if (k < 128) {
                v = uw1[(size_t)k * 128 + n];
            } else {
                int kk = k - 128;
                v = 0.f;
                for (int j = 0; j < 128; ++j)
                    v += mw2[(size_t)kk * 128 + j] * uw1[(size_t)(128 + j) * 128 + n];
            }
            g_wimg[HW_W1U + n * 264 + k] = __float2half_rn(v);
        } else {                              // W2U hi+lo
            u -= 57344; int n = u >> 7, k = u & 127;
            float v = uw2[(size_t)k * 128 + n];
            __half h = __float2half_rn(v);
            int row = fperm(n);
            g_wimg[HW_W2UH + row * 136 + k] = h;
            g_wimg[HW_W2UL + row * 136 + k] = __float2half_rn(v - __half2float(h));
        }
    }
    for (int t = g0; t < 128; t += gs) {
        float v = 0.f;
        for (int j = 0; j < 128; ++j)
            v += mb2[j] * uw1[(size_t)(128 + j) * 128 + t];
        g_vc[t] = v;
    }
    for (int i = g0; i < N * 64; i += gs) {
        float2 v = ((const float2*)nf)[i];
        __half h0 = __float2half_rn(v.x), h1 = __float2half_rn(v.y);
        ((uint32_t*)g_nfh)[i] = packh2(h0, h1);
        ((uint32_t*)g_nfl)[i] = packh2(__float2half_rn(v.x - __half2float(h0)),
                                       __float2half_rn(v.y - __half2float(h1)));
    }
    {
        const int* p32 = (const int*)ei;
        int s = 0;
        #pragma unroll
        for (int i = 0; i < 16; ++i) s |= p32[2 * i + 1];
        if (s == 0) {
            const long long* p = (const long long*)ei;
            for (int i = g0; i < E; i += gs) {
                g_src[i] = (int)p[i];
                g_dst[i] = (int)p[(size_t)E + i];
            }
        } else {
            for (int i = g0; i < E; i += gs) {
                g_src[i] = p32[i];
                g_dst[i] = p32[(size_t)E + i];
            }
        }
    }
    {
        float4 z = make_float4(0.f, 0.f, 0.f, 0.f);
        for (int i = g0; i < N * 32; i += gs) ((float4*)g_agg)[i] = z;
        for (int i = g0; i < N; i += gs) g_degf[i] = 0.f;
    }
}

// ---------------- P kernel: g_Ph = fp16(nf @ W1a + b1) ----------------
#define Q_W1  0
#define Q_XH  34816
#define Q_XL  69632
#define Q_B1  104448
#define Q_DYN 104960

__global__ __launch_bounds__(512, 1)
void pmat_kernel(const float* __restrict__ b1g, int N, int nTiles)
{
    extern __shared__ char smx[];
    const uint32_t sb = smem_u32(smx);
    float* sb1 = (float*)(smx + Q_B1);
    const int tid = threadIdx.x, lane = tid & 31, wid = tid >> 5;
    const int wm = wid & 3, wn = wid >> 2;

    if (tid < 128) sb1[tid] = b1g[tid];
    {
        const uint4* s = (const uint4*)((const char*)g_wimg + BW_W1MA);
        uint4* d = (uint4*)(smx + Q_W1);
        for (int i = tid; i < 2176; i += 512) d[i] = s[i];
    }

    for (int tile = blockIdx.x; tile < nTiles; tile += gridDim.x) {
        const int n0 = tile * 128;
        __syncthreads();
        for (int t = tid; t < 128 * 32; t += 512) {
            int row = t >> 5, ch = t & 31;
            int n = n0 + row; if (n >= N) n = N - 1;
            if (ch < 16)
                *(uint4*)(smx + Q_XH + row * 272 + ch * 16) = ((const uint4*)(g_nfh + (size_t)n * 128))[ch];
            else
                *(uint4*)(smx + Q_XL + row * 272 + (ch - 16) * 16) = ((const uint4*)(g_nfl + (size_t)n * 128))[ch - 16];
        }
        __syncthreads();

        float c[2][4][4];
        #pragma unroll
        for (int i = 0; i < 2; ++i)
            #pragma unroll
            for (int j = 0; j < 4; ++j)
                #pragma unroll
                for (int r = 0; r < 4; ++r) c[i][j][r] = 0.f;
        #pragma unroll
        for (int k = 0; k < 8; ++k)
            gemm_stepA2<272, 272>(c, sb + Q_XH, sb + Q_XL, sb + Q_W1,
                                  k * 32, k * 32, wm, wn, lane);

        const int q = lane & 3;
        const int Lb = wn * 32 + q * 8;
        float b0 = sb1[Lb],      b1v = sb1[Lb + 1], b2v = sb1[Lb + 2], b3v = sb1[Lb + 3];
        float b4v = sb1[Lb + 4], b5v = sb1[Lb + 5], b6v = sb1[Lb + 6], b7v = sb1[Lb + 7];
        #pragma unroll
        for (int mt = 0; mt < 2; ++mt) {
            int r = wm * 32 + mt * 16 + (lane >> 2);
            int nA = n0 + r, nB = n0 + r + 8;
            if (nA < N) {
                *(uint4*)(g_Ph + (size_t)nA * 128 + Lb) = make_uint4(
                    packh2(__float2half_rn(c[mt][0][0] + b0),  __float2half_rn(c[mt][0][1] + b1v)),
                    packh2(__float2half_rn(c[mt][1][0] + b2v), __float2half_rn(c[mt][1][1] + b3v)),
                    packh2(__float2half_rn(c[mt][2][0] + b4v), __float2half_rn(c[mt][2][1] + b5v)),
                    packh2(__float2half_rn(c[mt][3][0] + b6v), __float2half_rn(c[mt][3][1] + b7v)));
            }
            if (nB < N) {
                *(uint4*)(g_Ph + (size_t)nB * 128 + Lb) = make_uint4(
                    packh2(__float2half_rn(c[mt][0][2] + b0),  __float2half_rn(c[mt][0][3] + b1v)),
                    packh2(__float2half_rn(c[mt][1][2] + b2v), __float2half_rn(c[mt][1][3] + b3v)),
                    packh2(__float2half_rn(c[mt][2][2] + b4v), __float2half_rn(c[mt][2][3] + b5v)),
                    packh2(__float2half_rn(c[mt][3][2] + b6v), __float2half_rn(c[mt][3][3] + b7v)));
            }
        }
    }
}

// ---------------- edge kernel smem layout (bytes), 105 KB -> 2 blocks/SM ----
#define E_W1B 0        // W1Mb hi 18432 (stride 144)
#define E_X   18432    // X (ef fp16) 128x144 = 18432
#define E_EF  36864    // fp32 ef staging 128x256 = 32768
#define E_P   69632    // P fp16 single buf 128x272 = 34816
#define E_SRC 104448   // 128 ints
#define E_DYN 104960

__device__ __forceinline__ void issue_ef(char* smx, int tile, int E, int tid,
                                         const float* __restrict__ ef) {
    const uint32_t sf = smem_u32(smx) + E_EF;
    const int e0 = tile * 128;
    #pragma unroll
    for (int j = 0; j < 4; ++j) {
        int t = tid + j * 512;            // 0..2047
        int row = t >> 4, ch = t & 15;
        int e = e0 + row; if (e >= E) e = E - 1;
        cp16(sf + row * 256 + ch * 16, ef + (size_t)e * 64 + ch * 4);
    }
}
__device__ __forceinline__ void issue_p(char* smx, int tile, int E, int tid) {
    const uint32_t pb = smem_u32(smx) + E_P;
    const int e0 = tile * 128;
    #pragma unroll
    for (int j = 0; j < 4; ++j) {
        int t = tid + j * 512;            // 0..2047
        int row = t >> 4, ch = t & 15;
        int e = e0 + row; if (e >= E) e = E - 1;
        int dn = g_dst[e];
        cp16(pb + row * 272 + ch * 16, g_Ph + (size_t)dn * 128 + ch * 8);
    }
}

__global__ __launch_bounds__(512, 2)
void edge_mma_kernel(const float* __restrict__ edge_feats, int E, int nTiles)
{
    extern __shared__ char smx[];
    const uint32_t sb = smem_u32(smx);
    int* s_src = (int*)(smx + E_SRC);
    const int tid = threadIdx.x, lane = tid & 31, wid = tid >> 5;
    const int wm = wid & 3, wn = wid >> 2;

    {
        const uint4* s1 = (const uint4*)((const char*)g_wimg + BW_W1MB);
        uint4* d1 = (uint4*)(smx + E_W1B);
        for (int i = tid; i < 1152; i += 512) d1[i] = s1[i];
    }

    int tile = blockIdx.x;
    if (tile < nTiles) issue_ef(smx, tile, E, tid, edge_feats);
    CP_COMMIT();                                     // group: EF(t0)

    for (; tile < nTiles; tile += gridDim.x) {
        CP_WAIT0();          // EF(t) landed (and all older groups)
        __syncthreads();     // also orders prev epilogue before s_src/P/X reuse

        // s_src + deg (once per tile)
        if (tid < 128) {
            int e = tile * 128 + tid;
            int s = (e < E) ? g_src[e] : -1;
            s_src[tid] = s;
            if (s >= 0) red_add_f(g_degf + s, 1.0f);
        }
        // convert fp32 ef staging -> fp16 X (stride 144)
        for (int t = tid; t < 1024; t += 512) {
            int row = t >> 3, q = t & 7;
            const float4* sp = (const float4*)(smx + E_EF + row * 256 + q * 32);
            float4 v0 = sp[0], v1 = sp[1];
            *(uint4*)(smx + E_X + row * 144 + q * 16) = make_uint4(
                packh2(__float2half_rn(v0.x), __float2half_rn(v0.y)),
                packh2(__float2half_rn(v0.z), __float2half_rn(v0.w)),
                packh2(__float2half_rn(v1.x), __float2half_rn(v1.y)),
                packh2(__float2half_rn(v1.z), __float2half_rn(v1.w)));
        }
        __syncthreads();     // X built, EF consumed, s_src visible

        issue_p(smx, tile, E, tid);
        CP_COMMIT();                                 // group A: P(t)
        int nt = tile + gridDim.x;
        if (nt < nTiles) issue_ef(smx, nt, E, tid, edge_feats);
        CP_COMMIT();                                 // group B: EF(t+1)

        // GEMM1: K=64, 1-term (ef @ W1b) — overlaps P(t) and EF(t+1) loads
        float c[2][4][4];
        #pragma unroll
        for (int i = 0; i < 2; ++i)
            #pragma unroll
            for (int j = 0; j < 4; ++j)
                #pragma unroll
                for (int r = 0; r < 4; ++r) c[i][j][r] = 0.f;
        #pragma unroll
        for (int k = 0; k < 4; ++k)
            gemm_step1<144, 144>(c, sb + E_X, sb + E_W1B, k * 32, k * 32, wm, wn, lane);

        CP_WAIT1();          // P(t) done (EF(t+1) may still be in flight)
        __syncthreads();

        // epilogue: H = lrelu(c + P), scatter-add to g_agg
        {
            const int q = lane & 3;
            const int Lb = wn * 32 + q * 8;
            #pragma unroll
            for (int mt = 0; mt < 2; ++mt) {
                int r = wm * 32 + mt * 16 + (lane >> 2);
                int s0 = s_src[r], s1 = s_src[r + 8];
                uint4 pa = *(uint4*)(smx + E_P + r * 272 + Lb * 2);
                uint4 pbv = *(uint4*)(smx + E_P + (r + 8) * 272 + Lb * 2);
                if (s0 >= 0) {
                    float2 a0 = unp2(pa.x), a1 = unp2(pa.y), a2 = unp2(pa.z), a3 = unp2(pa.w);
                    float* p = g_agg + (size_t)s0 * 128 + Lb;
                    red_add_v4(p,
                        lrelu(c[mt][0][0] + a0.x), lrelu(c[mt][0][1] + a0.y),
                        lrelu(c[mt][1][0] + a1.x), lrelu(c[mt][1][1] + a1.y));
                    red_add_v4(p + 4,
                        lrelu(c[mt][2][0] + a2.x), lrelu(c[mt][2][1] + a2.y),
                        lrelu(c[mt][3][0] + a3.x), lrelu(c[mt][3][1] + a3.y));
                }
                if (s1 >= 0) {
                    float2 b0 = unp2(pbv.x), b1 = unp2(pbv.y), b2 = unp2(pbv.z), b3 = unp2(pbv.w);
                    float* p = g_agg + (size_t)s1 * 128 + Lb;
                    red_add_v4(p,
                        lrelu(c[mt][0][2] + b0.x), lrelu(c[mt][0][3] + b0.y),
                        lrelu(c[mt][1][2] + b1.x), lrelu(c[mt][1][3] + b1.y));
                    red_add_v4(p + 4,
                        lrelu(c[mt][2][2] + b2.x), lrelu(c[mt][2][3] + b2.y),
                        lrelu(c[mt][3][2] + b3.x), lrelu(c[mt][3][3] + b3.y));
                }
            }
        }
    }
}

// ---------------- persistent node kernel smem layout (bytes) ----------------
#define P_W1  0        // W1U hi (k>=128 rows = Wc), stride 528, 67584
#define P_W2H 67584
#define P_W2L 102400
#define P_XH  137216
#define P_XL  172032
#define P_SB1 206848
#define P_SB2 207360
#define P_VC  207872
#define P_DEG 208384
#define P_DYN 208896

__global__ __launch_bounds__(512, 1)
void node_mma_kernel(const float* __restrict__ b1g, const float* __restrict__ b2g,
                     float* __restrict__ out, int N, int nTiles)
{
    extern __shared__ char smx[];
    const uint32_t sb = smem_u32(smx);
    float* sb1  = (float*)(smx + P_SB1);
    float* sb2  = (float*)(smx + P_SB2);
    float* svc  = (float*)(smx + P_VC);
    float* sdeg = (float*)(smx + P_DEG);
    const int tid = threadIdx.x, lane = tid & 31, wid = tid >> 5;
    const int wm = wid & 3, wn = wid >> 2;

    if (tid < 128)      sb1[tid] = b1g[tid];
    else if (tid < 256) sb2[tid - 128] = b2g[tid - 128];
    else if (tid < 384) svc[tid - 256] = g_vc[tid - 256];
    {
        const uint4* s1 = (const uint4*)((const char*)g_wimg + BW_W1U);
        uint4* d1 = (uint4*)(smx + P_W1);
        for (int i = tid; i < 4224; i += 512) d1[i] = s1[i];
        const uint4* s2 = (const uint4*)((const char*)g_wimg + BW_W2U);
        uint4* d2 = (uint4*)(smx + P_W2H);
        for (int i = tid; i < 4352; i += 512) d2[i] = s2[i];
    }

    for (int tile = blockIdx.x; tile < nTiles; tile += gridDim.x) {
        const int n0 = tile * 128;
        __syncthreads();

        for (int t = tid; t < 128 * 32; t += 512) {
            int row = t >> 5, ch = t & 31;
            int n = n0 + row; if (n >= N) n = N - 1;
            if (ch < 16)
                *(uint4*)(smx + P_XH + row * 272 + ch * 16) = ((const uint4*)(g_nfh + (size_t)n * 128))[ch];
            else
                *(uint4*)(smx + P_XL + row * 272 + (ch - 16) * 16) = ((const uint4*)(g_nfl + (size_t)n * 128))[ch - 16];
        }
        if (tid < 128) {
            int n = n0 + tid;
            sdeg[tid] = (n < N) ? g_degf[n] : 0.f;
        }
        __syncthreads();

        float c[2][4][4];
        #pragma unroll
        for (int i = 0; i < 2; ++i)
            #pragma unroll
            for (int j = 0; j < 4; ++j)
                #pragma unroll
                for (int r = 0; r < 4; ++r) c[i][j][r] = 0.f;
        #pragma unroll
        for (int k = 0; k < 8; ++k)
            gemm_stepA2<272, 528>(c, sb + P_XH, sb + P_XL, sb + P_W1,
                                  k * 32, k * 32, wm, wn, lane);
        __syncthreads();

        for (int t = tid; t < 128 * 16; t += 512) {
            int row = t >> 4, ch = t & 15;
            int n = n0 + row; if (n >= N) n = N - 1;
            const float4* bp = (const float4*)(g_agg + (size_t)n * 128 + ch * 8);
            uint4 hi, lo;
            splitpack8(bp[0], bp[1], hi, lo);
            *(uint4*)(smx + P_XH + row * 272 + ch * 16) = hi;
            *(uint4*)(smx + P_XL + row * 272 + ch * 16) = lo;
        }
        __syncthreads();
        #pragma unroll
        for (int k = 0; k < 8; ++k)
            gemm_stepA2<272, 528>(c, sb + P_XH, sb + P_XL, sb + P_W1,
                                  k * 32, 256 + k * 32, wm, wn, lane);
        __syncthreads();

        #pragma unroll
        for (int mt = 0; mt < 2; ++mt)
            #pragma unroll
            for (int nt = 0; nt < 4; ++nt) {
                int r0  = wm * 32 + mt * 16 + (lane >> 2);
                int col = wn * 32 + nt * 8 + (lane & 3) * 2;
                float dA = sdeg[r0], dB = sdeg[r0 + 8];
                float vca = svc[col], vcb = svc[col + 1];
                float ba = sb1[col], bb = sb1[col + 1];
                float f0 = lrelu(c[mt][nt][0] + ba + dA * vca), f1 = lrelu(c[mt][nt][1] + bb + dA * vcb);
                float f2 = lrelu(c[mt][nt][2] + ba + dB * vca), f3 = lrelu(c[mt][nt][3] + bb + dB * vcb);
                __half h0 = __float2half_rn(f0), h1 = __float2half_rn(f1);
                __half h2 = __float2half_rn(f2), h3 = __float2half_rn(f3);
                *(uint32_t*)(smx + P_XH + r0 * 272 + col * 2)       = packh2(h0, h1);
                *(uint32_t*)(smx + P_XH + (r0 + 8) * 272 + col * 2) = packh2(h2, h3);
                *(uint32_t*)(smx + P_XL + r0 * 272 + col * 2) =
                    packh2(__float2half_rn(f0 - __half2float(h0)), __float2half_rn(f1 - __half2float(h1)));
                *(uint32_t*)(smx + P_XL + (r0 + 8) * 272 + col * 2) =
                    packh2(__float2half_rn(f2 - __half2float(h2)), __float2half_rn(f3 - __half2float(h3)));
            }
        __syncthreads();

        #pragma unroll
        for (int i = 0; i < 2; ++i)
            #pragma unroll
            for (int j = 0; j < 4; ++j)
                #pragma unroll
                for (int r = 0; r < 4; ++r) c[i][j][r] = 0.f;
        #pragma unroll
        for (int k = 0; k < 8; ++k)
            gemm_step3<272, 272>(c, sb + P_XH, sb + P_XL, sb + P_W2H, sb + P_W2L,
                                 k * 32, k * 32, wm, wn, lane);

        {
            const int q = lane & 3;
            const int Lb = wn * 32 + q * 8;
            float c0 = sb2[Lb],     c1 = sb2[Lb + 1], c2 = sb2[Lb + 2], c3 = sb2[Lb + 3];
            float c4 = sb2[Lb + 4], c5 = sb2[Lb + 5], c6 = sb2[Lb + 6], c7 = sb2[Lb + 7];
            #pragma unroll
            for (int mt = 0; mt < 2; ++mt) {
                int r = wm * 32 + mt * 16 + (lane >> 2);
                int nA = n0 + r, nB = n0 + r + 8;
                if (nA < N) {
                    float4* p = (float4*)(out + (size_t)nA * 128 + Lb);
                    p[0] = make_float4(c[mt][0][0] + c0, c[mt][0][1] + c1, c[mt][1][0] + c2, c[mt][1][1] + c3);
                    p[1] = make_float4(c[mt][2][0] + c4, c[mt][2][1] + c5, c[mt][3][0] + c6, c[mt][3][1] + c7);
                }
                if (nB < N) {
                    float4* p = (float4*)(out + (size_t)nB * 128 + Lb);
                    p[0] = make_float4(c[mt][0][2] + c0, c[mt][0][3] + c1, c[mt][1][2] + c2, c[mt][1][3] + c3);
                    p[1] = make_float4(c[mt][2][2] + c4, c[mt][2][3] + c5, c[mt][3][2] + c6, c[mt][3][3] + c7);
                }
            }
        }
    }
}

// ---------------------------------------------------------------------------

extern "C" void kernel_launch(void* const* d_in, const int* in_sizes, int n_in,
                              void* d_out, int out_size)
{
    const float* node_feats = (const float*)d_in[0];
    const float* edge_feats = (const float*)d_in[1];
    const float* msg_w1     = (const float*)d_in[2];
    const float* msg_b1     = (const float*)d_in[3];
    const float* msg_w2     = (const float*)d_in[4];
    const float* msg_b2     = (const float*)d_in[5];
    const float* upd_w1     = (const float*)d_in[6];
    const float* upd_b1     = (const float*)d_in[7];
    const float* upd_w2     = (const float*)d_in[8];
    const float* upd_b2     = (const float*)d_in[9];
    const void*  edge_index = d_in[10];

    const int N = in_sizes[0] / 128;   // 50000
    const int E = in_sizes[1] / 64;    // 800000
    const int nTiles  = (E + 127) / 128;
    const int nNTiles = (N + 127) / 128;

    cudaFuncSetAttribute(pmat_kernel,     cudaFuncAttributeMaxDynamicSharedMemorySize, Q_DYN);
    cudaFuncSetAttribute(edge_mma_kernel, cudaFuncAttributeMaxDynamicSharedMemorySize, E_DYN);
    cudaFuncSetAttribute(node_mma_kernel, cudaFuncAttributeMaxDynamicSharedMemorySize, P_DYN);

    prep_kernel<<<1024, 256>>>(node_feats, msg_w1, msg_w2, msg_b2,
                               upd_w1, upd_w2, edge_index, N, E);

    pmat_kernel<<<148, 512, Q_DYN>>>(msg_b1, N, nNTiles);

    edge_mma_kernel<<<296, 512, E_DYN>>>(edge_feats, E, nTiles);

    node_mma_kernel<<<148, 512, P_DYN>>>(upd_b1, upd_b2, (float*)d_out, N, nNTiles);
}